// round 16
// baseline (speedup 1.0000x reference)
#include <cuda_runtime.h>
#include <cuda_fp16.h>
#include <cstdint>

// Problem constants (fixed by the dataset)
#define NC   1000      // cells
#define NGOI 500       // genes of interest
#define NGT  5000      // total genes
#define NL   10        // latent dim
#define NK   129       // knots (NBINS+1)
#define RSB  136       // B row stride in halves (272B rows, 16B-aligned)
#define SERS 136       // shared E row stride in halves
#define SWRS 132       // shared W row stride in halves
#define CSPLIT 40
#define CPB  25        // cells per chunk
#define NBKT (NGOI * CSPLIT)   // 20000 buckets = (gene, chunk)
#define SEG  4                 // scatter sub-segments per bucket
#define SEGCAP 40              // slots per segment (mean 12.5, +7.8 sigma)
#define BKTMAX (SEG * SEGCAP)  // 160 records per bucket (mean 50)
#define MAXCUTS 1000000

// ---------------- device scratch (static: no allocation allowed) -------------
__device__ float  g_logits[NC * NGT];                 // 20 MB NORMALIZED logits
__device__ __align__(16) __half g_B[NGOI * RSB];      // exp(baseline), knots 0..128
__device__ int    g_scnt[NBKT * SEG];                 // segment cursors/counts
__device__ __align__(16) uint4 g_rec[(size_t)NBKT * SEG * SEGCAP]; // 51 MB
__device__ double g_part[NBKT];

// ---------------- kernel 1: baseline exp table + zero segment counts ----------
__global__ void k_bexp(const float* __restrict__ sb, const int* __restrict__ goi) {
    int j = blockIdx.x;
    int gene = goi[j];
    int t = threadIdx.x;
    if (t < NK)
        g_B[j * RSB + t] = __float2half_rn(__expf(sb[(size_t)gene * NK + t]));
    if (t < CSPLIT * SEG) g_scnt[j * CSPLIT * SEG + t] = 0;
}

// ------ kernel 2: per-cell LSE + store NORMALIZED logits (two-pass) -----------
__global__ void __launch_bounds__(512) k_lse2b(const float* __restrict__ latent,
                                               const float* __restrict__ wo,
                                               const float* __restrict__ ob) {
    __shared__ float slat[8 * NL];
    __shared__ float sred[16 * 8];
    __shared__ float slse[8];
    int c0 = blockIdx.x * 8;
    int tid = threadIdx.x;
    if (tid < 8 * NL) slat[tid] = latent[c0 * NL + tid];
    __syncthreads();
    float s[8];
#pragma unroll
    for (int c = 0; c < 8; c++) s[c] = 0.f;
    for (int g = tid; g < NGT; g += 512) {
        float w[NL];
#pragma unroll
        for (int l = 0; l < NL; l++) w[l] = wo[g * NL + l];
        float base = ob[g];
#pragma unroll
        for (int c = 0; c < 8; c++) {
            float a = base;
#pragma unroll
            for (int l = 0; l < NL; l++) a = fmaf(slat[c * NL + l], w[l], a);
            s[c] += __expf(a);
        }
    }
#pragma unroll
    for (int c = 0; c < 8; c++)
#pragma unroll
        for (int o = 16; o; o >>= 1) s[c] += __shfl_xor_sync(0xffffffffu, s[c], o);
    int w = tid >> 5, lane = tid & 31;
    if (lane == 0) {
#pragma unroll
        for (int c = 0; c < 8; c++) sred[w * 8 + c] = s[c];
    }
    __syncthreads();
    if (tid < 8) {
        float t = 0.f;
        for (int k = 0; k < 16; k++) t += sred[k * 8 + tid];
        slse[tid] = __logf(t);
    }
    __syncthreads();
    float lse[8];
#pragma unroll
    for (int c = 0; c < 8; c++) lse[c] = slse[c];
    for (int g = tid; g < NGT; g += 512) {
        float w[NL];
#pragma unroll
        for (int l = 0; l < NL; l++) w[l] = wo[g * NL + l];
        float base = ob[g];
#pragma unroll
        for (int c = 0; c < 8; c++) {
            float a = base;
#pragma unroll
            for (int l = 0; l < NL; l++) a = fmaf(slat[c * NL + l], w[l], a);
            g_logits[(c0 + c) * NGT + g] = a - lse[c];
        }
    }
}

// --------- kernel 3: capacity-slot scatter + logit prefetch into record -------
__global__ void k_scatter(const float* __restrict__ coord,
                          const int*   __restrict__ cxg,
                          const int*   __restrict__ lcxg,
                          const int*   __restrict__ gloc,
                          int ncuts) {
    int i = blockIdx.x * 256 + threadIdx.x;
    if (i >= ncuts) return;
    unsigned p = (unsigned)cxg[i];
    unsigned j = p % NGOI, cell = p / NGOI;
    unsigned chunk = cell / CPB;
    unsigned cl = cell - chunk * CPB;
    int bkt = j * CSPLIT + chunk;
    int seg = i & (SEG - 1);
    float nl = __ldg(&g_logits[(unsigned)lcxg[i]]);   // MLP-rich prefetch
    int pos = atomicAdd(&g_scnt[bkt * SEG + seg], 1);
    if (pos < SEGCAP) {
        uint4 rec;
        rec.x = __float_as_uint(coord[i]);
        rec.y = __float_as_uint(nl);                  // normalized logit
        rec.z = (cl << 9) | (unsigned)gloc[i];
        rec.w = 0u;
        g_rec[((size_t)bkt * SEG + seg) * SEGCAP + pos] = rec;
    }
}

// ---------------- kernel 4 (PROFILED): fused E-in-shared + per-cut spline -----
// Block = (gene j, chunk of 25 cells). W in shared; E rows for occupied cells
// in shared; 8-lane-group cut loop with logit already in the record.
__global__ void __launch_bounds__(256, 6) k_fused(const float* __restrict__ latent,
                                                  const float* __restrict__ hw,
                                                  const int*   __restrict__ goi) {
    __shared__ __align__(16) __half  sE[CPB * SERS];     // 6800 B
    __shared__ __align__(8)  __half  sW[NL * SWRS];      // 2640 B
    __shared__ __align__(16) uint4  srec[BKTMAX];        // 2560 B
    __shared__ int      spre[SEG + 1];
    __shared__ unsigned smask;
    __shared__ double   sdbl[8];
    int j = blockIdx.x, chunk = blockIdx.y;
    int bkt = j * CSPLIT + chunk;
    int gene = goi[j];
    int c0 = chunk * CPB;
    int tid = threadIdx.x;
    int w = tid >> 5, lane = tid & 31;
    const float C = 4.852030263919617f + 8.517193191416238f; // ln(128)+ln(5000)
    const unsigned FULL = 0xffffffffu;

    if (tid == 0) {
        smask = 0u;
        int acc = 0;
        for (int s = 0; s < SEG; s++) {
            spre[s] = acc;
            int n = g_scnt[bkt * SEG + s];
            acc += (n < SEGCAP) ? n : SEGCAP;
        }
        spre[SEG] = acc;
    }
    // stage W tile (knots 0..127) into shared as half
    const float* wp = hw + (size_t)gene * NL * NK;
    for (int i = tid; i < NL * 128; i += 256) {
        int l = i >> 7, k = i & 127;
        sW[l * SWRS + k] = __float2half_rn(wp[l * NK + k]);
    }
    __syncthreads();

    // compact segments into srec + build cell-occupancy mask
    for (int s = 0; s < SEG; s++) {
        int n = spre[s + 1] - spre[s];
        const uint4* src = &g_rec[((size_t)bkt * SEG + s) * SEGCAP];
        for (int k = tid; k < n; k += 256) {
            uint4 rec = src[k];
            srec[spre[s] + k] = rec;
            atomicOr(&smask, 1u << (rec.z >> 9));
        }
    }
    __syncthreads();

    unsigned occmask = smask;
    // knot-128 side pass (occupied cells only; 25 threads)
    if (tid < CPB && ((occmask >> tid) & 1u)) {
        float a = 0.f;
#pragma unroll
        for (int l = 0; l < NL; l++)
            a = fmaf(__ldg(&latent[(c0 + tid) * NL + l]), __ldg(&wp[l * NK + 128]), a);
        sE[tid * SERS + 128] = __float2half_rn(__expf(a));
    }

    // ---- Phase A: E rows for occupied cells (warp per cell, lane = 4 knots) --
    int k4 = lane * 4;
    for (int c = w; c < CPB; c += 8) {
        if (!((occmask >> c) & 1u)) continue;
        const float* lp = &latent[(c0 + c) * NL];
        __half2 a01 = __float2half2_rn(0.f);
        __half2 a23 = __float2half2_rn(0.f);
#pragma unroll
        for (int l = 0; l < NL; l++) {
            __half2 lv = __float2half2_rn(__ldg(&lp[l]));     // warp-uniform LDG
            uint2 wv = *(const uint2*)&sW[l * SWRS + k4];     // LDS.64, lane-own
            a01 = __hfma2(lv, *(__half2*)&wv.x, a01);
            a23 = __hfma2(lv, *(__half2*)&wv.y, a23);
        }
        float2 f01 = __half22float2(a01);
        float2 f23 = __half22float2(a23);
        __half2 h01 = __floats2half2_rn(__expf(f01.x), __expf(f01.y));
        __half2 h23 = __floats2half2_rn(__expf(f23.x), __expf(f23.y));
        uint2 st;
        st.x = *(const unsigned*)&h01;
        st.y = *(const unsigned*)&h23;
        *(uint2*)&sE[c * SERS + k4] = st;
    }
    __syncthreads();

    // ---- Phase B: cuts, 8-lane groups, 4 cuts per warp -----------------------
    int total = spre[SEG];
    int grp = lane >> 3, sub = lane & 7;
    double acc = 0.0;

    for (int base = w * 4; base < total; base += 32) {
        int cut = base + grp;
        int cc = (cut < total) ? cut : (total - 1);
        uint4 rec = srec[cc];
        int gl = rec.z & 511;
        int cl = rec.z >> 9;

        const __half* er = &sE[cl * SERS + sub * 16];
        const __half* br = &g_B[gl * RSB + sub * 16];
        uint4 ev0 = *(const uint4*)er;
        uint4 ev1 = *(const uint4*)(er + 8);
        uint4 bv0 = *(const uint4*)br;
        uint4 bv1 = *(const uint4*)(br + 8);

        __half2 t0 = __hmul2(*(const __half2*)&ev0.x, *(const __half2*)&bv0.x);
        __half2 t1 = __hmul2(*(const __half2*)&ev0.y, *(const __half2*)&bv0.y);
        __half2 t2 = __hmul2(*(const __half2*)&ev0.z, *(const __half2*)&bv0.z);
        __half2 t3 = __hmul2(*(const __half2*)&ev0.w, *(const __half2*)&bv0.w);
        __half2 t4 = __hmul2(*(const __half2*)&ev1.x, *(const __half2*)&bv1.x);
        __half2 t5 = __hmul2(*(const __half2*)&ev1.y, *(const __half2*)&bv1.y);
        __half2 t6 = __hmul2(*(const __half2*)&ev1.z, *(const __half2*)&bv1.z);
        __half2 t7 = __hmul2(*(const __half2*)&ev1.w, *(const __half2*)&bv1.w);

        __half2 t = __hadd2(__hadd2(__hadd2(t0, t1), __hadd2(t2, t3)),
                            __hadd2(__hadd2(t4, t5), __hadd2(t6, t7)));
        float2 tf = __half22float2(t);
        float s = tf.x + tf.y;
        if (sub == 0) s -= 0.5f * __low2float(t0);          // halve bottom endpoint
        if (sub == 7) {
            float u128 = __half2float(sE[cl * SERS + 128]) *
                         __half2float(g_B[gl * RSB + 128]);
            s += 0.5f * u128;                                // top endpoint (half)
        }
        s += __shfl_xor_sync(FULL, s, 1);
        s += __shfl_xor_sync(FULL, s, 2);
        s += __shfl_xor_sync(FULL, s, 4);

        if (sub == 0 && cut < total) {
            float x  = __uint_as_float(rec.x);
            float nl = __uint_as_float(rec.y);              // prefetched logit

            float xs = fminf(fmaxf(x, 0.f), 0.999999f) * 128.f;
            int bi = (int)xs; if (bi > 127) bi = 127;
            float alpha = xs - (float)bi;

            float L = __half2float(sE[cl * SERS + bi])     * __half2float(g_B[gl * RSB + bi]);
            float R = __half2float(sE[cl * SERS + bi + 1]) * __half2float(g_B[gl * RSB + bi + 1]);
            float val = __logf(fmaf(alpha, R - L, L)) - __logf(s) + C + nl;
            acc += (double)val;
        }
    }

    // deterministic block reduce
#pragma unroll
    for (int o = 16; o; o >>= 1)
        acc += __shfl_xor_sync(FULL, acc, o);
    if (lane == 0) sdbl[w] = acc;
    __syncthreads();
    if (tid == 0) {
        double t = 0.0;
        for (int k = 0; k < 8; k++) t += sdbl[k];
        g_part[bkt] = t;
    }
}

// ---------------- kernel 5: deterministic final reduce -------------------------
__global__ void k_final(float* __restrict__ out) {
    __shared__ double sh[256];
    double t = 0.0;
    for (int i = threadIdx.x; i < NBKT; i += 256) t += g_part[i];
    sh[threadIdx.x] = t;
    __syncthreads();
    for (int s = 128; s; s >>= 1) {
        if (threadIdx.x < s) sh[threadIdx.x] += sh[threadIdx.x + s];
        __syncthreads();
    }
    if (threadIdx.x == 0) out[0] = (float)(-sh[0]);   // elbo = -sum(likelihood)
}

// ---------------- launch ------------------------------------------------------
extern "C" void kernel_launch(void* const* d_in, const int* in_sizes, int n_in,
                              void* d_out, int out_size) {
    const float* latent = (const float*)d_in[0];
    const float* coord  = (const float*)d_in[1];
    const int*   goi    = (const int*)  d_in[2];
    const int*   cxg    = (const int*)  d_in[3];   // cut_local_cellxgene_ix
    const int*   lcxg   = (const int*)  d_in[4];   // cut_localcellxgene_ix
    const int*   gloc   = (const int*)  d_in[5];   // cut_local_gene_ix
    const float* hw     = (const float*)d_in[6];   // height_slope_w
    const float* wo     = (const float*)d_in[7];   // overall_slope_w
    const float* ob     = (const float*)d_in[8];   // overall_baseline
    const float* sb     = (const float*)d_in[9];   // spline_baseline
    float* out = (float*)d_out;
    int ncuts = in_sizes[1];
    if (ncuts > MAXCUTS) ncuts = MAXCUTS;

    k_bexp<<<NGOI, 160>>>(sb, goi);                                        // #1
    k_lse2b<<<NC / 8, 512>>>(latent, wo, ob);                              // #2
    k_scatter<<<(ncuts + 255) / 256, 256>>>(coord, cxg, lcxg, gloc, ncuts);// #3
    {
        dim3 grid(NGOI, CSPLIT);
        k_fused<<<grid, 256>>>(latent, hw, goi);                           // #4 (profiled)
    }
    k_final<<<1, 256>>>(out);                                              // #5
}

// round 17
// speedup vs baseline: 1.3859x; 1.3859x over previous
#include <cuda_runtime.h>
#include <cuda_fp16.h>
#include <cstdint>

// Problem constants (fixed by the dataset)
#define NC   1000      // cells
#define NGOI 500       // genes of interest
#define NGT  5000      // total genes
#define NL   10        // latent dim
#define NK   129       // knots (NBINS+1)
#define RSB  136       // B row stride in halves (272B rows, 16B-aligned)
#define SERS 136       // shared E row stride in halves
#define SWRS 132       // shared W row stride in halves
#define CSPLIT 8
#define CPB  125       // cells per chunk
#define NBKT (NGOI * CSPLIT)   // 4000 buckets = (gene, chunk)
#define SEG  8                 // scatter sub-segments per bucket
#define SEGCAP 96              // slots per segment (mean 31.25, +11 sigma)
#define BKTMAX 448             // compacted records per bucket (mean 250)
#define MAXCUTS 1000000

// ---------------- device scratch (static: no allocation allowed) -------------
__device__ float  g_logits[NC * NGT];                 // 20 MB raw logits
__device__ float  g_lse[NC];
__device__ __align__(16) __half g_B[NGOI * RSB];      // exp(baseline), knots 0..128
__device__ int    g_scnt[NBKT * SEG];                 // segment cursors/counts
__device__ __align__(16) uint4 g_rec[(size_t)NBKT * SEG * SEGCAP]; // 49 MB
__device__ double g_part[NBKT];

// ---------------- kernel 1: baseline exp table + zero segment counts ----------
__global__ void k_bexp(const float* __restrict__ sb, const int* __restrict__ goi) {
    int j = blockIdx.x;
    int gene = goi[j];
    int t = threadIdx.x;
    if (t < NK)
        g_B[j * RSB + t] = __float2half_rn(__expf(sb[(size_t)gene * NK + t]));
    if (t < CSPLIT * SEG) g_scnt[j * CSPLIT * SEG + t] = 0;
}

// ------ kernel 2: logits + per-cell LSE (single pass, stores raw logits) ------
__global__ void __launch_bounds__(512) k_lse(const float* __restrict__ latent,
                                             const float* __restrict__ wo,
                                             const float* __restrict__ ob) {
    __shared__ float slat[8 * NL];
    __shared__ float sred[16 * 8];
    int c0 = blockIdx.x * 8;
    int tid = threadIdx.x;
    if (tid < 8 * NL) slat[tid] = latent[c0 * NL + tid];
    __syncthreads();
    float s[8];
#pragma unroll
    for (int c = 0; c < 8; c++) s[c] = 0.f;
    for (int g = tid; g < NGT; g += 512) {
        float w[NL];
#pragma unroll
        for (int l = 0; l < NL; l++) w[l] = wo[g * NL + l];
        float base = ob[g];
#pragma unroll
        for (int c = 0; c < 8; c++) {
            float a = base;
#pragma unroll
            for (int l = 0; l < NL; l++) a = fmaf(slat[c * NL + l], w[l], a);
            g_logits[(c0 + c) * NGT + g] = a;
            s[c] += __expf(a);
        }
    }
#pragma unroll
    for (int c = 0; c < 8; c++)
#pragma unroll
        for (int o = 16; o; o >>= 1) s[c] += __shfl_xor_sync(0xffffffffu, s[c], o);
    int w = tid >> 5, lane = tid & 31;
    if (lane == 0) {
#pragma unroll
        for (int c = 0; c < 8; c++) sred[w * 8 + c] = s[c];
    }
    __syncthreads();
    if (tid < 8) {
        float t = 0.f;
        for (int k = 0; k < 16; k++) t += sred[k * 8 + tid];
        g_lse[c0 + tid] = __logf(t);
    }
}

// ------ kernel 3: scatter with full per-cut precompute -------------------------
// rec = { nl, alpha, bi<<16 | cl<<9 | gl, 0 }
__global__ void k_scatter(const float* __restrict__ coord,
                          const int*   __restrict__ cxg,
                          const int*   __restrict__ lcxg,
                          const int*   __restrict__ gloc,
                          int ncuts) {
    int i = blockIdx.x * 256 + threadIdx.x;
    if (i >= ncuts) return;
    unsigned p = (unsigned)cxg[i];
    unsigned j = p % NGOI, cell = p / NGOI;
    unsigned chunk = cell / CPB;
    unsigned cl = cell - chunk * CPB;
    int bkt = j * CSPLIT + chunk;
    int seg = i & (SEG - 1);

    unsigned q = (unsigned)lcxg[i];
    float nl = __ldg(&g_logits[q]) - __ldg(&g_lse[q / (unsigned)NGT]);

    float x = __ldg(&coord[i]);
    float xs = fminf(fmaxf(x, 0.f), 0.999999f) * 128.f;
    int bi = (int)xs; if (bi > 127) bi = 127;
    float alpha = xs - (float)bi;

    int pos = atomicAdd(&g_scnt[bkt * SEG + seg], 1);
    if (pos < SEGCAP) {
        uint4 rec;
        rec.x = __float_as_uint(nl);
        rec.y = __float_as_uint(alpha);
        rec.z = ((unsigned)bi << 16) | (cl << 9) | (unsigned)gloc[i];
        rec.w = 0u;
        g_rec[((size_t)bkt * SEG + seg) * SEGCAP + pos] = rec;
    }
}

// ---------------- kernel 4 (PROFILED): fused E-in-shared + per-cut spline -----
__global__ void __launch_bounds__(256) k_fused(const float* __restrict__ latent,
                                               const float* __restrict__ hw,
                                               const int*   __restrict__ goi) {
    __shared__ __align__(16) __half  sE[CPB * SERS];     // 34000 B
    __shared__ __align__(8)  __half  sW[NL * SWRS];      // 2640 B
    __shared__ __align__(16) uint4  srec[BKTMAX];        // 7168 B
    __shared__ int      spre[SEG + 1];
    __shared__ unsigned smask[4];
    __shared__ double   sdbl[8];
    int j = blockIdx.x, chunk = blockIdx.y;
    int bkt = j * CSPLIT + chunk;
    int gene = goi[j];
    int c0 = chunk * CPB;
    int tid = threadIdx.x;
    int w = tid >> 5, lane = tid & 31;
    const float C = 4.852030263919617f + 8.517193191416238f; // ln(128)+ln(5000)
    const unsigned FULL = 0xffffffffu;

    if (tid < 4) smask[tid] = 0u;
    if (tid == 0) {
        int acc = 0;
        for (int s = 0; s < SEG; s++) {
            spre[s] = acc;
            int n = g_scnt[bkt * SEG + s];
            if (n > SEGCAP) n = SEGCAP;
            acc += n;
            if (acc > BKTMAX) acc = BKTMAX;
        }
        spre[SEG] = acc;
    }
    // stage W tile (knots 0..127) into shared as half
    const float* wp = hw + (size_t)gene * NL * NK;
    for (int i = tid; i < NL * 128; i += 256) {
        int l = i >> 7, k = i & 127;
        sW[l * SWRS + k] = __float2half_rn(wp[l * NK + k]);
    }
    __syncthreads();

    // compact segments into srec + build cell-occupancy mask
    for (int s = 0; s < SEG; s++) {
        int n = spre[s + 1] - spre[s];
        const uint4* src = &g_rec[((size_t)bkt * SEG + s) * SEGCAP];
        for (int k = tid; k < n; k += 256) {
            uint4 rec = src[k];
            srec[spre[s] + k] = rec;
            unsigned cl = (rec.z >> 9) & 127u;
            atomicOr(&smask[cl >> 5], 1u << (cl & 31));
        }
    }
    __syncthreads();

    // knot-128 side pass (occupied cells only)
    if (tid < CPB && ((smask[tid >> 5] >> (tid & 31)) & 1u)) {
        float a = 0.f;
#pragma unroll
        for (int l = 0; l < NL; l++)
            a = fmaf(__ldg(&latent[(c0 + tid) * NL + l]), __ldg(&wp[l * NK + 128]), a);
        sE[tid * SERS + 128] = __float2half_rn(__expf(a));
    }

    // ---- Phase A: E rows, 2 cells per warp-iteration (ILP) -------------------
    int k4 = lane * 4;
    for (int c = w; c < CPB; c += 16) {
        int cA = c, cB = c + 8;
        bool aOn = (smask[cA >> 5] >> (cA & 31)) & 1u;
        bool bOn = (cB < CPB) && ((smask[cB >> 5] >> (cB & 31)) & 1u);
        if (!aOn && !bOn) continue;
        const float* lpA = &latent[(c0 + cA) * NL];
        const float* lpB = &latent[(c0 + cB) * NL];
        __half2 zero = __float2half2_rn(0.f);
        __half2 aA01 = zero, aA23 = zero, aB01 = zero, aB23 = zero;
#pragma unroll
        for (int l = 0; l < NL; l++) {
            uint2 wv = *(const uint2*)&sW[l * SWRS + k4];
            __half2 w01 = *(__half2*)&wv.x, w23 = *(__half2*)&wv.y;
            if (aOn) {
                __half2 lv = __float2half2_rn(__ldg(&lpA[l]));
                aA01 = __hfma2(lv, w01, aA01);
                aA23 = __hfma2(lv, w23, aA23);
            }
            if (bOn) {
                __half2 lv = __float2half2_rn(__ldg(&lpB[l]));
                aB01 = __hfma2(lv, w01, aB01);
                aB23 = __hfma2(lv, w23, aB23);
            }
        }
        if (aOn) {
            float2 f01 = __half22float2(aA01);
            float2 f23 = __half22float2(aA23);
            __half2 h01 = __floats2half2_rn(__expf(f01.x), __expf(f01.y));
            __half2 h23 = __floats2half2_rn(__expf(f23.x), __expf(f23.y));
            uint2 st; st.x = *(const unsigned*)&h01; st.y = *(const unsigned*)&h23;
            *(uint2*)&sE[cA * SERS + k4] = st;
        }
        if (bOn) {
            float2 f01 = __half22float2(aB01);
            float2 f23 = __half22float2(aB23);
            __half2 h01 = __floats2half2_rn(__expf(f01.x), __expf(f01.y));
            __half2 h23 = __floats2half2_rn(__expf(f23.x), __expf(f23.y));
            uint2 st; st.x = *(const unsigned*)&h01; st.y = *(const unsigned*)&h23;
            *(uint2*)&sE[cB * SERS + k4] = st;
        }
    }
    __syncthreads();

    // ---- Phase B: cuts, 8-lane groups, 4 cuts per warp -----------------------
    int total = spre[SEG];
    int grp = lane >> 3, sub = lane & 7;
    double acc = 0.0;

    for (int base = w * 4; base < total; base += 32) {
        int cut = base + grp;
        int cc = (cut < total) ? cut : (total - 1);
        uint4 rec = srec[cc];
        int gl = rec.z & 511;
        int cl = (rec.z >> 9) & 127;
        int bi = rec.z >> 16;

        const __half* er = &sE[cl * SERS + sub * 16];
        const __half* br = &g_B[gl * RSB + sub * 16];
        uint4 ev0 = *(const uint4*)er;
        uint4 ev1 = *(const uint4*)(er + 8);
        uint4 bv0 = *(const uint4*)br;
        uint4 bv1 = *(const uint4*)(br + 8);

        // norm via two HFMA2 chains (t0 kept for the bottom endpoint)
        __half2 t0 = __hmul2(*(const __half2*)&ev0.x, *(const __half2*)&bv0.x);
        __half2 ca = __hfma2(*(const __half2*)&ev0.y, *(const __half2*)&bv0.y, t0);
        ca = __hfma2(*(const __half2*)&ev0.z, *(const __half2*)&bv0.z, ca);
        ca = __hfma2(*(const __half2*)&ev0.w, *(const __half2*)&bv0.w, ca);
        __half2 cb = __hmul2(*(const __half2*)&ev1.x, *(const __half2*)&bv1.x);
        cb = __hfma2(*(const __half2*)&ev1.y, *(const __half2*)&bv1.y, cb);
        cb = __hfma2(*(const __half2*)&ev1.z, *(const __half2*)&bv1.z, cb);
        cb = __hfma2(*(const __half2*)&ev1.w, *(const __half2*)&bv1.w, cb);
        __half2 t = __hadd2(ca, cb);
        float2 tf = __half22float2(t);
        float s = tf.x + tf.y;
        if (sub == 0) s -= 0.5f * __low2float(t0);          // halve bottom endpoint
        if (sub == 7) {
            float u128 = __half2float(sE[cl * SERS + 128]) *
                         __half2float(g_B[gl * RSB + 128]);
            s += 0.5f * u128;                                // top endpoint (half)
        }
        s += __shfl_xor_sync(FULL, s, 1);
        s += __shfl_xor_sync(FULL, s, 2);
        s += __shfl_xor_sync(FULL, s, 4);

        if (sub == 0 && cut < total) {
            float nl    = __uint_as_float(rec.x);
            float alpha = __uint_as_float(rec.y);
            float L = __half2float(sE[cl * SERS + bi])     * __half2float(g_B[gl * RSB + bi]);
            float R = __half2float(sE[cl * SERS + bi + 1]) * __half2float(g_B[gl * RSB + bi + 1]);
            float val = __logf(fmaf(alpha, R - L, L)) - __logf(s) + C + nl;
            acc += (double)val;
        }
    }

    // deterministic block reduce
#pragma unroll
    for (int o = 16; o; o >>= 1)
        acc += __shfl_xor_sync(FULL, acc, o);
    if (lane == 0) sdbl[w] = acc;
    __syncthreads();
    if (tid == 0) {
        double t = 0.0;
        for (int k = 0; k < 8; k++) t += sdbl[k];
        g_part[bkt] = t;
    }
}

// ---------------- kernel 5: deterministic final reduce -------------------------
__global__ void k_final(float* __restrict__ out) {
    __shared__ double sh[256];
    double t = 0.0;
    for (int i = threadIdx.x; i < NBKT; i += 256) t += g_part[i];
    sh[threadIdx.x] = t;
    __syncthreads();
    for (int s = 128; s; s >>= 1) {
        if (threadIdx.x < s) sh[threadIdx.x] += sh[threadIdx.x + s];
        __syncthreads();
    }
    if (threadIdx.x == 0) out[0] = (float)(-sh[0]);   // elbo = -sum(likelihood)
}

// ---------------- launch ------------------------------------------------------
extern "C" void kernel_launch(void* const* d_in, const int* in_sizes, int n_in,
                              void* d_out, int out_size) {
    const float* latent = (const float*)d_in[0];
    const float* coord  = (const float*)d_in[1];
    const int*   goi    = (const int*)  d_in[2];
    const int*   cxg    = (const int*)  d_in[3];   // cut_local_cellxgene_ix
    const int*   lcxg   = (const int*)  d_in[4];   // cut_localcellxgene_ix
    const int*   gloc   = (const int*)  d_in[5];   // cut_local_gene_ix
    const float* hw     = (const float*)d_in[6];   // height_slope_w
    const float* wo     = (const float*)d_in[7];   // overall_slope_w
    const float* ob     = (const float*)d_in[8];   // overall_baseline
    const float* sb     = (const float*)d_in[9];   // spline_baseline
    float* out = (float*)d_out;
    int ncuts = in_sizes[1];
    if (ncuts > MAXCUTS) ncuts = MAXCUTS;

    k_bexp<<<NGOI, 160>>>(sb, goi);                                        // #1
    k_lse<<<NC / 8, 512>>>(latent, wo, ob);                                // #2
    k_scatter<<<(ncuts + 255) / 256, 256>>>(coord, cxg, lcxg, gloc, ncuts);// #3
    {
        dim3 grid(NGOI, CSPLIT);
        k_fused<<<grid, 256>>>(latent, hw, goi);                           // #4 (profiled)
    }
    k_final<<<1, 256>>>(out);                                              // #5
}